// round 3
// baseline (speedup 1.0000x reference)
#include <cuda_runtime.h>
#include <math.h>
#include <stdint.h>

// Problem dims (fixed by the dataset)
#define HD   512          // H
#define PD   256          // P (complex modes) -> 512 interleaved reals
#define LD   4096         // L
#define BSZ  8
#define MROWS (BSZ*LD)    // 32768
#define CH   64           // scan chunk length
#define NCH  (LD/CH)      // 64 chunks

// ---------------- scratch (device globals: no allocation allowed) ----------
__device__ __align__(16) float  g_Bu[(size_t)MROWS*HD];   // 64 MB, interleaved complex (re,im)
__device__ __align__(16) float  g_W1[HD*HD];              // 1 MB
__device__ __align__(16) float  g_W2[HD*HD];              // 1 MB
__device__ float2 g_lambda[PD];
__device__ float2 g_lamS[PD];
__device__ float2 g_coef[PD];
__device__ float2 g_bout [BSZ*NCH*PD];
__device__ float2 g_carry[BSZ*NCH*PD];

// ---------------- packed f32x2 helpers -------------------------------------
__device__ __forceinline__ unsigned long long pack_dup(float a) {
    unsigned int u = __float_as_uint(a);
    unsigned long long r;
    asm("mov.b64 %0, {%1, %1};" : "=l"(r) : "r"(u));
    return r;
}
__device__ __forceinline__ void fma2(unsigned long long &d,
                                     unsigned long long a, unsigned long long b) {
    asm("fma.rn.f32x2 %0, %1, %2, %0;" : "+l"(d) : "l"(a), "l"(b));
}
__device__ __forceinline__ float2 unpack2(unsigned long long v) {
    unsigned int lo, hi;
    asm("mov.b64 {%0, %1}, %2;" : "=r"(lo), "=r"(hi) : "l"(v));
    return make_float2(__uint_as_float(lo), __uint_as_float(hi));
}

// ---------------- prep: discretization + weight assembly --------------------
__global__ void prep1_kernel(const float* __restrict__ Lre,
                             const float* __restrict__ Lim,
                             const float* __restrict__ logstep) {
    int p = threadIdx.x;
    if (p >= PD) return;
    double lre = (double)Lre[p], lim = (double)Lim[p];
    double st  = exp((double)logstep[p]);
    double ar = lre * st, ai = lim * st;
    double er = exp(ar);
    double lr = er * cos(ai), li = er * sin(ai);          // lambda_bar
    g_lambda[p] = make_float2((float)lr, (float)li);
    double eS = exp(ar * (double)CH);                     // lambda_bar^CH
    g_lamS[p]  = make_float2((float)(eS * cos(ai * (double)CH)),
                             (float)(eS * sin(ai * (double)CH)));
    // coef = (lambda_bar - 1) / Lam  (complex divide)
    double nr = lr - 1.0, ni = li;
    double d2 = lre * lre + lim * lim;
    g_coef[p] = make_float2((float)((nr * lre + ni * lim) / d2),
                            (float)((ni * lre - nr * lim) / d2));
}

__global__ void prep2_kernel(const float* __restrict__ B,
                             const float* __restrict__ C) {
    int tot = HD * HD;
    for (int idx = blockIdx.x * blockDim.x + threadIdx.x;
         idx < 2 * tot; idx += gridDim.x * blockDim.x) {
        if (idx < tot) {
            // W1[h][n] : n=2p -> Re(B_bar[p][h]), n=2p+1 -> Im(B_bar[p][h])
            int h = idx >> 9, n = idx & 511;
            int p = n >> 1;
            float2 c = g_coef[p];
            float b0 = B[((size_t)p * HD + h) * 2 + 0];
            float b1 = B[((size_t)p * HD + h) * 2 + 1];
            g_W1[idx] = (n & 1) ? fmaf(c.x, b1,  c.y * b0)
                                : fmaf(c.x, b0, -c.y * b1);
        } else {
            // W2[k][h] : k=2p -> 2*Cre[h][p], k=2p+1 -> -2*Cim[h][p]
            int j = idx - tot;
            int k = j >> 9, h = j & 511;
            int p = k >> 1;
            float cv = C[((size_t)h * PD + p) * 2 + (k & 1)];
            g_W2[j] = (k & 1) ? (-2.0f * cv) : (2.0f * cv);
        }
    }
}

// ---------------- 3-pass chunked complex scan over L -------------------------
// pass 1: per-(b,chunk,p) local inclusive scan in place; emit chunk-final state
__global__ void scan1_kernel() {
    int tid = blockIdx.x * 256 + threadIdx.x;    // 131072 threads
    int p = tid & (PD - 1);
    int c = (tid >> 8) & (NCH - 1);
    int b = tid >> 14;
    float2 lam = g_lambda[p];
    float xr = 0.f, xi = 0.f;
    float2* base = (float2*)g_Bu + ((size_t)(b * LD + c * CH)) * PD + p;
    #pragma unroll 8
    for (int j = 0; j < CH; j++) {
        float2 v = base[(size_t)j * PD];
        float nr = fmaf(lam.x, xr, fmaf(-lam.y, xi, v.x));
        float ni = fmaf(lam.y, xr, fmaf( lam.x, xi, v.y));
        xr = nr; xi = ni;
        base[(size_t)j * PD] = make_float2(xr, xi);
    }
    g_bout[(b * NCH + c) * PD + p] = make_float2(xr, xi);
}

// pass 2: per-(b,p) scan over chunk carries
__global__ void scan2_kernel() {
    int b = blockIdx.x;
    int p = threadIdx.x;
    float2 lS = g_lamS[p];
    float cr = 0.f, ci = 0.f;
    for (int c = 0; c < NCH; c++) {
        int idx = (b * NCH + c) * PD + p;
        g_carry[idx] = make_float2(cr, ci);
        float2 bo = g_bout[idx];
        float nr = fmaf(lS.x, cr, fmaf(-lS.y, ci, bo.x));
        float ni = fmaf(lS.y, cr, fmaf( lS.x, ci, bo.y));
        cr = nr; ci = ni;
    }
}

// pass 3: fixup: xs[l] = local[l] + lambda^{j+1} * carry_in
__global__ void scan3_kernel() {
    int tid = blockIdx.x * 256 + threadIdx.x;
    int p = tid & (PD - 1);
    int c = (tid >> 8) & (NCH - 1);
    int b = tid >> 14;
    if (c == 0) return;                          // carry is zero
    float2 car = g_carry[(b * NCH + c) * PD + p];
    float2 lam = g_lambda[p];
    float tr = lam.x * car.x - lam.y * car.y;    // lambda^1 * carry
    float ti = lam.x * car.y + lam.y * car.x;
    float2* base = (float2*)g_Bu + ((size_t)(b * LD + c * CH)) * PD + p;
    #pragma unroll 8
    for (int j = 0; j < CH; j++) {
        float2 v = base[(size_t)j * PD];
        v.x += tr; v.y += ti;
        base[(size_t)j * PD] = v;
        float nr = lam.x * tr - lam.y * ti;
        float ni = lam.x * ti + lam.y * tr;
        tr = nr; ti = ni;
    }
}

// ---------------- SGEMM (f32x2 packed), 128x128 tile, BK=16, 8x8/thread ------
// MODE 0: Cout(g_Bu) = Aext(x) @ g_W1
// MODE 1: Cout(ext)  = g_Bu @ g_W2  + D*x epilogue
template <int MODE>
__global__ __launch_bounds__(256, 2)
void sgemm_kernel(const float* __restrict__ Aext,
                  float* __restrict__ Cext,
                  const float* __restrict__ skipX,
                  const float* __restrict__ Dv) {
    __shared__ float As[16][128];   // transposed: As[k][m]
    __shared__ float Bs[16][128];   // Bs[k][n]

    const float* A = (MODE == 0) ? Aext : g_Bu;
    const float* W = (MODE == 0) ? g_W1 : g_W2;
    float*       Co = (MODE == 0) ? g_Bu : Cext;

    int tid = threadIdx.x;
    int tx = tid & 15;            // n-direction (8 cols each)
    int ty = tid >> 4;            // m-direction (8 rows each)
    int row0 = blockIdx.y * 128;
    int col0 = blockIdx.x * 128;

    // loader indices
    int ar = tid >> 2;            // 0..63
    int ac = (tid & 3) * 4;       // 0,4,8,12
    int wr = tid >> 5;            // 0..7
    int wc = (tid & 31) * 4;      // 0..124

    unsigned long long acc[8][4];
    #pragma unroll
    for (int i = 0; i < 8; i++)
        #pragma unroll
        for (int j = 0; j < 4; j++) acc[i][j] = 0ull;

    for (int kt = 0; kt < 512; kt += 16) {
        float4 a0 = *(const float4*)&A[(size_t)(row0 + ar     ) * 512 + kt + ac];
        float4 a1 = *(const float4*)&A[(size_t)(row0 + ar + 64) * 512 + kt + ac];
        float4 w0 = *(const float4*)&W[(size_t)(kt + wr    ) * 512 + col0 + wc];
        float4 w1 = *(const float4*)&W[(size_t)(kt + wr + 8) * 512 + col0 + wc];

        __syncthreads();   // previous tile consumed
        As[ac + 0][ar] = a0.x; As[ac + 1][ar] = a0.y;
        As[ac + 2][ar] = a0.z; As[ac + 3][ar] = a0.w;
        As[ac + 0][ar + 64] = a1.x; As[ac + 1][ar + 64] = a1.y;
        As[ac + 2][ar + 64] = a1.z; As[ac + 3][ar + 64] = a1.w;
        *(float4*)&Bs[wr    ][wc] = w0;
        *(float4*)&Bs[wr + 8][wc] = w1;
        __syncthreads();

        #pragma unroll
        for (int k = 0; k < 16; k++) {
            float4 af0 = *(const float4*)&As[k][ty * 8];
            float4 af1 = *(const float4*)&As[k][ty * 8 + 4];
            ulonglong2 b01 = *(const ulonglong2*)&Bs[k][tx * 8];
            ulonglong2 b23 = *(const ulonglong2*)&Bs[k][tx * 8 + 4];
            unsigned long long bb0 = b01.x, bb1 = b01.y, bb2 = b23.x, bb3 = b23.y;
            float av[8] = {af0.x, af0.y, af0.z, af0.w, af1.x, af1.y, af1.z, af1.w};
            #pragma unroll
            for (int i = 0; i < 8; i++) {
                unsigned long long ad = pack_dup(av[i]);
                fma2(acc[i][0], ad, bb0);
                fma2(acc[i][1], ad, bb1);
                fma2(acc[i][2], ad, bb2);
                fma2(acc[i][3], ad, bb3);
            }
        }
    }

    // epilogue
    int n0 = col0 + tx * 8;
    float dv[8];
    if (MODE == 1) {
        #pragma unroll
        for (int j = 0; j < 8; j++) dv[j] = Dv[n0 + j];
    }
    #pragma unroll
    for (int i = 0; i < 8; i++) {
        int m = row0 + ty * 8 + i;
        float out[8];
        #pragma unroll
        for (int j = 0; j < 4; j++) {
            float2 v = unpack2(acc[i][j]);
            out[2 * j] = v.x; out[2 * j + 1] = v.y;
        }
        if (MODE == 1) {
            const float* xr = &skipX[(size_t)m * 512 + n0];
            float4 x0 = *(const float4*)&xr[0];
            float4 x1 = *(const float4*)&xr[4];
            out[0] = fmaf(dv[0], x0.x, out[0]);
            out[1] = fmaf(dv[1], x0.y, out[1]);
            out[2] = fmaf(dv[2], x0.z, out[2]);
            out[3] = fmaf(dv[3], x0.w, out[3]);
            out[4] = fmaf(dv[4], x1.x, out[4]);
            out[5] = fmaf(dv[5], x1.y, out[5]);
            out[6] = fmaf(dv[6], x1.z, out[6]);
            out[7] = fmaf(dv[7], x1.w, out[7]);
        }
        *(float4*)&Co[(size_t)m * 512 + n0    ] = make_float4(out[0], out[1], out[2], out[3]);
        *(float4*)&Co[(size_t)m * 512 + n0 + 4] = make_float4(out[4], out[5], out[6], out[7]);
    }
}

// ---------------- launch -----------------------------------------------------
extern "C" void kernel_launch(void* const* d_in, const int* in_sizes, int n_in,
                              void* d_out, int out_size) {
    const float* x       = (const float*)d_in[0];   // (8,4096,512)
    const float* Lre     = (const float*)d_in[1];   // (256)
    const float* Lim     = (const float*)d_in[2];   // (256)
    const float* B       = (const float*)d_in[3];   // (256,512,2)
    const float* C       = (const float*)d_in[4];   // (512,256,2)
    const float* D       = (const float*)d_in[5];   // (512)
    const float* logstep = (const float*)d_in[6];   // (256)
    float* out = (float*)d_out;                     // (8,4096,512) fp32

    prep1_kernel<<<1, 256>>>(Lre, Lim, logstep);
    prep2_kernel<<<256, 256>>>(B, C);

    dim3 gemm_grid(HD / 128, MROWS / 128);          // (4, 256)
    sgemm_kernel<0><<<gemm_grid, 256>>>(x, nullptr, nullptr, nullptr);

    scan1_kernel<<<(BSZ * NCH * PD) / 256, 256>>>();  // 512 blocks
    scan2_kernel<<<BSZ, PD>>>();
    scan3_kernel<<<(BSZ * NCH * PD) / 256, 256>>>();

    sgemm_kernel<1><<<gemm_grid, 256>>>(nullptr, out, x, D);
}